// round 11
// baseline (speedup 1.0000x reference)
#include <cuda_runtime.h>
#include <cuda_bf16.h>
#include <math.h>
#include <stdint.h>

// Laplace diagonal recurrence:
//   out[t, i, f] = e[i] * out[t-1, i, f] + decay[i] * inp[t, f]
// T = 2048, N_S = 108, F = 256, fp32.
//
// R11: fair TMA-store test. Compute identical to R10 (GI=12, f32x2 math,
// PF=8 register input pipeline, CHUNK=128/WARM=64), but outputs staged in
// smem double buffers (8 rows x 12KB = 96KB each) and drained with
// cp.async.bulk (12KB contiguous per row). One bulk group outstanding;
// sync once per 8 rows. 256 threads (iq 0..3 x 3 i-states), 144 blocks.

constexpr int T_LEN  = 2048;
constexpr int F      = 256;
constexpr int NS     = 108;
constexpr int CHUNK  = 128;
constexpr int WARM   = 64;
constexpr int NCHUNK = T_LEN / CHUNK;   // 16
constexpr int KI     = 3;               // i-states per thread
constexpr int GI     = 12;              // i per block (4 iq groups x 3)
constexpr int NIB    = NS / GI;         // 9
constexpr int PF     = 8;               // input prefetch depth (rows)
constexpr int F4     = F / 4;           // 64
constexpr int TR     = 8;               // rows per output tile
constexpr int THR    = 256;
constexpr int ROW_BYTES = GI * F * 4;           // 12288
constexpr int TILE_F4   = TR * GI * F4;         // 6144 float4 = 96KB
constexpr int SMEM_BYTES = 2 * TILE_F4 * 16;    // 196608

typedef unsigned long long u64;
typedef unsigned int       u32;

__device__ __forceinline__ u64 fma2(u64 a, u64 b, u64 c) {
    u64 d;
    asm("fma.rn.f32x2 %0, %1, %2, %3;" : "=l"(d) : "l"(a), "l"(b), "l"(c));
    return d;
}
__device__ __forceinline__ u64 mul2(u64 a, u64 b) {
    u64 d;
    asm("mul.rn.f32x2 %0, %1, %2;" : "=l"(d) : "l"(a), "l"(b));
    return d;
}
__device__ __forceinline__ u64 pack2(float lo, float hi) {
    u64 d;
    asm("mov.b64 %0, {%1, %2};" : "=l"(d) : "f"(lo), "f"(hi));
    return d;
}

union V4 {
    float4 f;
    u64    u[2];
};

__device__ __forceinline__ void bulk_store(const void* gdst, const void* ssrc, u32 bytes) {
    u32 sa = (u32)__cvta_generic_to_shared(ssrc);
    asm volatile("cp.async.bulk.global.shared::cta.bulk_group [%0], [%1], %2;"
                 :: "l"(gdst), "r"(sa), "r"(bytes) : "memory");
}
__device__ __forceinline__ void bulk_commit() {
    asm volatile("cp.async.bulk.commit_group;" ::: "memory");
}
__device__ __forceinline__ void bulk_wait_read1() {
    asm volatile("cp.async.bulk.wait_group.read 1;" ::: "memory");
}
__device__ __forceinline__ void bulk_wait_all() {
    asm volatile("cp.async.bulk.wait_group 0;" ::: "memory");
}
__device__ __forceinline__ void fence_async() {
    asm volatile("fence.proxy.async;" ::: "memory");
}

__global__ __launch_bounds__(THR, 1)
void laplace_kernel(const float* __restrict__ inp, float* __restrict__ out) {
    extern __shared__ float4 sbuf[];   // [2][TR][GI][F4]

    const int tid = threadIdx.x;
    const int fq  = tid & 63;          // float4 lane
    const int iq  = tid >> 6;          // 0..3
    const int ib  = blockIdx.x;        // 0..8
    const int chunk = blockIdx.y;      // 0..15

    // Per-i constants (double precision; matches reference ~1e-7).
    u64 e2[KI], d2[KI];
    const double c = pow(20.0, 1.0 / 99.0) - 1.0;
    #pragma unroll
    for (int k = 0; k < KI; k++) {
        int i = ib * GI + iq * KI + k;
        double tau = pow(1.0 + c, (double)(i - 4));
        double s   = 4.0 / tau;
        double ed  = exp(-s);
        float ef = (float)ed;
        float df = (float)((1.0 - ed) / s);
        e2[k] = pack2(ef, ef);
        d2[k] = pack2(df, df);
    }

    const int t_start = chunk * CHUNK;
    const int warm    = (t_start < WARM) ? t_start : WARM;  // 0 or 64
    const int t0      = t_start - warm;
    const int steps   = warm + CHUNK;                        // 128 or 192
    const int ntiles  = steps / TR;                          // 16 or 24
    const int wtiles  = warm / TR;                           // 0 or 8

    const float4* __restrict__ ip = reinterpret_cast<const float4*>(inp)
                                    + (size_t)t0 * F4 + fq;

    // Scaled states: st' = e*st' + x;  out = dcy * st'.
    u64 st[KI][2];
    #pragma unroll
    for (int k = 0; k < KI; k++) { st[k][0] = 0ull; st[k][1] = 0ull; }

    // Prime the register input pipeline (PF == TR).
    V4 pf[PF];
    #pragma unroll
    for (int j = 0; j < PF; j++) pf[j].f = __ldg(ip + j * F4);

    int s = 0;
    // ---- warm tiles (no stores) ----
    for (; s < wtiles; s++) {
        #pragma unroll
        for (int j = 0; j < TR; j++) {
            const int t  = s * TR + j;
            const u64 x0 = pf[j].u[0];
            const u64 x1 = pf[j].u[1];
            const int tn = t + PF;
            if (tn < steps) pf[j].f = __ldg(ip + (size_t)tn * F4);
            #pragma unroll
            for (int k = 0; k < KI; k++) {
                st[k][0] = fma2(e2[k], st[k][0], x0);
                st[k][1] = fma2(e2[k], st[k][1], x1);
            }
        }
    }

    // ---- storing tiles: fill smem buffer, drain via cp.async.bulk ----
    const char* gout = reinterpret_cast<const char*>(out);
    const size_t i_off = (size_t)(ib * GI) * 1024;   // byte offset within a t-row

    for (int ot = 0; s < ntiles; s++, ot++) {
        if (ot >= 2) {                      // recycle buf[ot&1]
            if (tid == 0) bulk_wait_read1();
            __syncthreads();
        }
        float4* buf = &sbuf[(ot & 1) * TILE_F4];

        #pragma unroll
        for (int j = 0; j < TR; j++) {
            const int t  = s * TR + j;
            const u64 x0 = pf[j].u[0];
            const u64 x1 = pf[j].u[1];
            const int tn = t + PF;
            if (tn < steps) pf[j].f = __ldg(ip + (size_t)tn * F4);
            #pragma unroll
            for (int k = 0; k < KI; k++) {
                st[k][0] = fma2(e2[k], st[k][0], x0);
                st[k][1] = fma2(e2[k], st[k][1], x1);
                V4 o;
                o.u[0] = mul2(d2[k], st[k][0]);
                o.u[1] = mul2(d2[k], st[k][1]);
                buf[(j * GI + iq * KI + k) * F4 + fq] = o.f;
            }
        }
        fence_async();
        __syncthreads();

        if (tid == 0) {
            const int tbase = t_start + ot * TR;
            #pragma unroll
            for (int r = 0; r < TR; r++) {
                const char* gdst = gout + (size_t)(tbase + r) * (NS * 1024) + i_off;
                bulk_store(gdst, &buf[r * GI * F4], ROW_BYTES);
            }
            bulk_commit();
        }
    }

    if (tid == 0) bulk_wait_all();
}

extern "C" void kernel_launch(void* const* d_in, const int* in_sizes, int n_in,
                              void* d_out, int out_size) {
    const float* inp = (const float*)d_in[0];
    float* out       = (float*)d_out;
    cudaFuncSetAttribute(laplace_kernel,
                         cudaFuncAttributeMaxDynamicSharedMemorySize, SMEM_BYTES);
    dim3 grid(NIB, NCHUNK);   // 9 x 16 = 144 blocks
    laplace_kernel<<<grid, THR, SMEM_BYTES>>>(inp, out);
}

// round 12
// speedup vs baseline: 1.0637x; 1.0637x over previous
#include <cuda_runtime.h>
#include <cuda_bf16.h>
#include <math.h>
#include <stdint.h>

// Laplace diagonal recurrence:
//   out[t, i, f] = e[i] * out[t-1, i, f] + decay[i] * inp[t, f]
// T = 2048, N_S = 108, F = 256, fp32.
//
// R12 = R10 (best, 73.8us) with ONE change: stores use st.global.cs.v4
// (evict-first). Model: kernel sits exactly on the ~6300 B/cyc
// path-independent LTS cap (L2% == 26% == cap/theoretical in every fast
// variant); .cs shortens dirty-line residency without changing the
// write-allocate path. Expected 0-3% gain, bounded downside.
//
// Config: 128 threads (fq 0..63 float4 lane, iq 0..1), 6 i-states per
// thread => GI=12 per block, NIB=9; CHUNK=128, WARM=64 (truncation
// e_max^64 ~ 1.2e-5 << 1e-3); PF=8 register input pipeline; f32x2 math.
// Grid = 9 x 16 = 144 blocks.

constexpr int T_LEN  = 2048;
constexpr int F      = 256;
constexpr int NS     = 108;
constexpr int CHUNK  = 128;
constexpr int WARM   = 64;
constexpr int NCHUNK = T_LEN / CHUNK;   // 16
constexpr int KI     = 6;               // i-states per thread
constexpr int GI     = 12;              // i-values per block
constexpr int NIB    = NS / GI;         // 9
constexpr int PF     = 8;               // prefetch depth (rows)
constexpr int F4     = F / 4;           // 64 float4 lanes per row

typedef unsigned long long u64;

__device__ __forceinline__ u64 fma2(u64 a, u64 b, u64 c) {
    u64 d;
    asm("fma.rn.f32x2 %0, %1, %2, %3;" : "=l"(d) : "l"(a), "l"(b), "l"(c));
    return d;
}
__device__ __forceinline__ u64 mul2(u64 a, u64 b) {
    u64 d;
    asm("mul.rn.f32x2 %0, %1, %2;" : "=l"(d) : "l"(a), "l"(b));
    return d;
}
__device__ __forceinline__ u64 pack2(float lo, float hi) {
    u64 d;
    asm("mov.b64 %0, {%1, %2};" : "=l"(d) : "f"(lo), "f"(hi));
    return d;
}
__device__ __forceinline__ void stcs4(float4* p, u64 lo, u64 hi) {
    asm volatile("st.global.cs.v4.b32 [%0], {%1, %2, %3, %4};"
                 :: "l"(p),
                    "r"((unsigned)(lo & 0xffffffffu)), "r"((unsigned)(lo >> 32)),
                    "r"((unsigned)(hi & 0xffffffffu)), "r"((unsigned)(hi >> 32))
                 : "memory");
}

union V4 {
    float4 f;
    u64    u[2];
};

__global__ __launch_bounds__(128, 1)
void laplace_kernel(const float* __restrict__ inp, float* __restrict__ out) {
    const int tid = threadIdx.x;
    const int fq  = tid & 63;        // float4 lane: f = 4*fq
    const int iq  = tid >> 6;        // 0..1 -> which half of the 12 i's
    const int ib  = blockIdx.x;      // 0..8
    const int chunk = blockIdx.y;    // 0..15

    // Per-i constants in double precision (matches reference ~1e-7).
    u64 e2[KI], d2[KI];
    const double c = pow(20.0, 1.0 / 99.0) - 1.0;
    #pragma unroll
    for (int k = 0; k < KI; k++) {
        int i = ib * GI + iq * KI + k;
        double tau = pow(1.0 + c, (double)(i - 4));
        double s   = 4.0 / tau;
        double ed  = exp(-s);
        float ef = (float)ed;
        float df = (float)((1.0 - ed) / s);
        e2[k] = pack2(ef, ef);
        d2[k] = pack2(df, df);
    }

    const int t_start = chunk * CHUNK;
    const int warm    = (t_start < WARM) ? t_start : WARM;  // 0 or 64
    const int t0      = t_start - warm;
    const int steps   = warm + CHUNK;                        // 128 or 192

    const float4* __restrict__ ip = reinterpret_cast<const float4*>(inp)
                                    + (size_t)t0 * F4 + fq;

    // Scaled states: st' = e*st' + x;  out = dcy * st'.
    u64 st[KI][2];
    #pragma unroll
    for (int k = 0; k < KI; k++) { st[k][0] = 0ull; st[k][1] = 0ull; }

    // Prime the register pipeline.
    V4 pf[PF];
    #pragma unroll
    for (int j = 0; j < PF; j++) pf[j].f = __ldg(ip + j * F4);

    // ---- warm-up (no stores), warm is 0 or 64, divisible by PF ----
    for (int tb = 0; tb < warm; tb += PF) {
        #pragma unroll
        for (int j = 0; j < PF; j++) {
            const int t  = tb + j;
            const u64 x0 = pf[j].u[0];
            const u64 x1 = pf[j].u[1];
            const int tn = t + PF;
            if (tn < steps) pf[j].f = __ldg(ip + (size_t)tn * F4);
            #pragma unroll
            for (int k = 0; k < KI; k++) {
                st[k][0] = fma2(e2[k], st[k][0], x0);
                st[k][1] = fma2(e2[k], st[k][1], x1);
            }
        }
    }

    // ---- main: CHUNK=128 stored rows, 6 STG.128.cs per thread per row ----
    float4* op = reinterpret_cast<float4*>(out)
               + ((size_t)t_start * NS + (size_t)(ib * GI + iq * KI)) * F4 + fq;
    for (int tb = 0; tb < CHUNK; tb += PF) {
        #pragma unroll
        for (int j = 0; j < PF; j++) {
            const int t  = warm + tb + j;
            const u64 x0 = pf[j].u[0];
            const u64 x1 = pf[j].u[1];
            const int tn = t + PF;
            if (tn < steps) pf[j].f = __ldg(ip + (size_t)tn * F4);
            #pragma unroll
            for (int k = 0; k < KI; k++) {
                st[k][0] = fma2(e2[k], st[k][0], x0);
                st[k][1] = fma2(e2[k], st[k][1], x1);
                u64 o0 = mul2(d2[k], st[k][0]);
                u64 o1 = mul2(d2[k], st[k][1]);
                stcs4(op + k * F4, o0, o1);
            }
            op += NS * F4;
        }
    }
}

extern "C" void kernel_launch(void* const* d_in, const int* in_sizes, int n_in,
                              void* d_out, int out_size) {
    const float* inp = (const float*)d_in[0];
    float* out       = (float*)d_out;
    dim3 grid(NIB, NCHUNK);   // 9 x 16 = 144 blocks
    laplace_kernel<<<grid, 128>>>(inp, out);
}

// round 13
// speedup vs baseline: 1.0656x; 1.0018x over previous
#include <cuda_runtime.h>
#include <cuda_bf16.h>
#include <math.h>
#include <stdint.h>

// Laplace diagonal recurrence:
//   out[t, i, f] = e[i] * out[t-1, i, f] + decay[i] * inp[t, f]
// T = 2048, N_S = 108, F = 256, fp32.
//
// R13 = R12 (best, 71.8us) + per-i-block warm-up lengths. Warm-up needed is
// ~11/s[i] steps (truncation e^-11 ~ 1.7e-5 << 1e-3); fast-decay blocks need
// only 8 rows, not 64. Table {8,8,8,16,16,24,32,48,64} by ib. Cuts input
// re-read LTS traffic ~60% and removes warm-up tail imbalance. Everything
// else identical: 128 thr, KI=6 (GI=12, NIB=9), CHUNK=128, PF=8, f32x2 math,
// st.global.cs.v4 stores, grid 9x16=144.

constexpr int T_LEN  = 2048;
constexpr int F      = 256;
constexpr int NS     = 108;
constexpr int CHUNK  = 128;
constexpr int NCHUNK = T_LEN / CHUNK;   // 16
constexpr int KI     = 6;               // i-states per thread
constexpr int GI     = 12;              // i-values per block
constexpr int NIB    = NS / GI;         // 9
constexpr int PF     = 8;               // prefetch depth (rows)
constexpr int F4     = F / 4;           // 64 float4 lanes per row

// Per-ib warm-up rows: ceil(11 / s_min(ib), 8), s_min = 4/tau(ib*12+11).
__device__ __constant__ int WTAB[NIB] = {8, 8, 8, 16, 16, 24, 32, 48, 64};

typedef unsigned long long u64;

__device__ __forceinline__ u64 fma2(u64 a, u64 b, u64 c) {
    u64 d;
    asm("fma.rn.f32x2 %0, %1, %2, %3;" : "=l"(d) : "l"(a), "l"(b), "l"(c));
    return d;
}
__device__ __forceinline__ u64 mul2(u64 a, u64 b) {
    u64 d;
    asm("mul.rn.f32x2 %0, %1, %2;" : "=l"(d) : "l"(a), "l"(b));
    return d;
}
__device__ __forceinline__ u64 pack2(float lo, float hi) {
    u64 d;
    asm("mov.b64 %0, {%1, %2};" : "=l"(d) : "f"(lo), "f"(hi));
    return d;
}
__device__ __forceinline__ void stcs4(float4* p, u64 lo, u64 hi) {
    asm volatile("st.global.cs.v4.b32 [%0], {%1, %2, %3, %4};"
                 :: "l"(p),
                    "r"((unsigned)(lo & 0xffffffffu)), "r"((unsigned)(lo >> 32)),
                    "r"((unsigned)(hi & 0xffffffffu)), "r"((unsigned)(hi >> 32))
                 : "memory");
}

union V4 {
    float4 f;
    u64    u[2];
};

__global__ __launch_bounds__(128, 1)
void laplace_kernel(const float* __restrict__ inp, float* __restrict__ out) {
    const int tid = threadIdx.x;
    const int fq  = tid & 63;        // float4 lane: f = 4*fq
    const int iq  = tid >> 6;        // 0..1 -> which half of the 12 i's
    const int ib  = blockIdx.x;      // 0..8
    const int chunk = blockIdx.y;    // 0..15

    // Per-i constants in double precision (matches reference ~1e-7).
    u64 e2[KI], d2[KI];
    const double c = pow(20.0, 1.0 / 99.0) - 1.0;
    #pragma unroll
    for (int k = 0; k < KI; k++) {
        int i = ib * GI + iq * KI + k;
        double tau = pow(1.0 + c, (double)(i - 4));
        double s   = 4.0 / tau;
        double ed  = exp(-s);
        float ef = (float)ed;
        float df = (float)((1.0 - ed) / s);
        e2[k] = pack2(ef, ef);
        d2[k] = pack2(df, df);
    }

    const int t_start = chunk * CHUNK;
    const int wneed   = WTAB[ib];                             // 8..64, mult of 8
    const int warm    = (t_start < wneed) ? t_start : wneed;  // 0 or wneed
    const int t0      = t_start - warm;
    const int steps   = warm + CHUNK;

    const float4* __restrict__ ip = reinterpret_cast<const float4*>(inp)
                                    + (size_t)t0 * F4 + fq;

    // Scaled states: st' = e*st' + x;  out = dcy * st'.
    u64 st[KI][2];
    #pragma unroll
    for (int k = 0; k < KI; k++) { st[k][0] = 0ull; st[k][1] = 0ull; }

    // Prime the register pipeline.
    V4 pf[PF];
    #pragma unroll
    for (int j = 0; j < PF; j++) pf[j].f = __ldg(ip + j * F4);

    // ---- warm-up (no stores); warm is 0 or a multiple of PF ----
    for (int tb = 0; tb < warm; tb += PF) {
        #pragma unroll
        for (int j = 0; j < PF; j++) {
            const int t  = tb + j;
            const u64 x0 = pf[j].u[0];
            const u64 x1 = pf[j].u[1];
            const int tn = t + PF;
            if (tn < steps) pf[j].f = __ldg(ip + (size_t)tn * F4);
            #pragma unroll
            for (int k = 0; k < KI; k++) {
                st[k][0] = fma2(e2[k], st[k][0], x0);
                st[k][1] = fma2(e2[k], st[k][1], x1);
            }
        }
    }

    // ---- main: CHUNK=128 stored rows, 6 STG.128.cs per thread per row ----
    float4* op = reinterpret_cast<float4*>(out)
               + ((size_t)t_start * NS + (size_t)(ib * GI + iq * KI)) * F4 + fq;
    for (int tb = 0; tb < CHUNK; tb += PF) {
        #pragma unroll
        for (int j = 0; j < PF; j++) {
            const int t  = warm + tb + j;
            const u64 x0 = pf[j].u[0];
            const u64 x1 = pf[j].u[1];
            const int tn = t + PF;
            if (tn < steps) pf[j].f = __ldg(ip + (size_t)tn * F4);
            #pragma unroll
            for (int k = 0; k < KI; k++) {
                st[k][0] = fma2(e2[k], st[k][0], x0);
                st[k][1] = fma2(e2[k], st[k][1], x1);
                u64 o0 = mul2(d2[k], st[k][0]);
                u64 o1 = mul2(d2[k], st[k][1]);
                stcs4(op + k * F4, o0, o1);
            }
            op += NS * F4;
        }
    }
}

extern "C" void kernel_launch(void* const* d_in, const int* in_sizes, int n_in,
                              void* d_out, int out_size) {
    const float* inp = (const float*)d_in[0];
    float* out       = (float*)d_out;
    dim3 grid(NIB, NCHUNK);   // 9 x 16 = 144 blocks
    laplace_kernel<<<grid, 128>>>(inp, out);
}